// round 8
// baseline (speedup 1.0000x reference)
#include <cuda_runtime.h>
#include <cuda_fp16.h>
#include <math.h>
#include <stdint.h>

#define D_MODEL 1024
#define D_INNER 2048
#define D_STATE 16
#define DT_RANK 64
#define CONV_K  4
#define BSZ     2
#define SEQ     2048
#define BL      (BSZ*SEQ)             // 4096
#define XDBL_C  (DT_RANK + 2*D_STATE) // 96
#define XPROJ_SPLITK 4

// ---------------- scratch (static device globals) ---------------------------
__device__ __align__(16) __half g_xn_hi[BL * D_MODEL];
__device__ __align__(16) __half g_xn_lo[BL * D_MODEL];
__device__ __align__(16) float  g_xz   [BL * 2 * D_INNER];
__device__ __align__(16) __half g_u_hi [BL * D_INNER];
__device__ __align__(16) __half g_u_lo [BL * D_INNER];
__device__ __align__(16) float  g_xdbl [BL * XDBL_C];
__device__ __align__(16) __half g_xd_hi[BL * XDBL_C];
__device__ __align__(16) __half g_xd_lo[BL * XDBL_C];
__device__ __align__(16) float  g_part [XPROJ_SPLITK * BL * XDBL_C];
__device__ __align__(16) float  g_dl   [BL * D_INNER];
__device__ __align__(16) __half g_y_hi [BL * D_INNER];
__device__ __align__(16) __half g_y_lo [BL * D_INNER];
__device__ __align__(16) __half g_wi_hi[2 * D_INNER * D_MODEL];
__device__ __align__(16) __half g_wi_lo[2 * D_INNER * D_MODEL];
__device__ __align__(16) __half g_xp_hi[XDBL_C * D_INNER];
__device__ __align__(16) __half g_xp_lo[XDBL_C * D_INNER];
__device__ __align__(16) __half g_dw_hi[D_INNER * DT_RANK];
__device__ __align__(16) __half g_dw_lo[D_INNER * DT_RANK];
__device__ __align__(16) __half g_wo_hi[D_MODEL * D_INNER];
__device__ __align__(16) __half g_wo_lo[D_MODEL * D_INNER];

// ---------------- helpers ----------------------------------------------------
__device__ __forceinline__ void cp16(void* dst_smem, const void* src, int sz) {
    uint32_t d = (uint32_t)__cvta_generic_to_shared(dst_smem);
    asm volatile("cp.async.cg.shared.global [%0], [%1], 16, %2;\n"
                 :: "r"(d), "l"(src), "r"(sz));
}
__device__ __forceinline__ void cp_commit() {
    asm volatile("cp.async.commit_group;\n");
}
template<int N_> __device__ __forceinline__ void cp_wait() {
    asm volatile("cp.async.wait_group %0;\n" :: "n"(N_));
}
__device__ __forceinline__ void h_split(float x, __half& h, __half& l) {
    h = __float2half_rn(x);
    l = __float2half_rn(x - __half2float(h));
}
__device__ __forceinline__ void h_split4(float4 v, uint2& hi, uint2& lo) {
    __half h0,l0,h1,l1,h2,l2,h3,l3;
    h_split(v.x,h0,l0); h_split(v.y,h1,l1);
    h_split(v.z,h2,l2); h_split(v.w,h3,l3);
    __half2 ha = __halves2half2(h0,h1), hb = __halves2half2(h2,h3);
    __half2 la = __halves2half2(l0,l1), lb = __halves2half2(l2,l3);
    hi.x = *(uint32_t*)&ha; hi.y = *(uint32_t*)&hb;
    lo.x = *(uint32_t*)&la; lo.y = *(uint32_t*)&lb;
}
// fp16 inputs, fp32 accumulator (main term)
__device__ __forceinline__ void mma16(float* c, const uint32_t* a, const uint32_t* b) {
    asm volatile(
        "mma.sync.aligned.m16n8k16.row.col.f32.f16.f16.f32 "
        "{%0,%1,%2,%3}, {%4,%5,%6,%7}, {%8,%9}, {%0,%1,%2,%3};\n"
        : "+f"(c[0]), "+f"(c[1]), "+f"(c[2]), "+f"(c[3])
        : "r"(a[0]), "r"(a[1]), "r"(a[2]), "r"(a[3]), "r"(b[0]), "r"(b[1]));
}
// fp16 inputs, fp16 accumulator (cross terms; possible 2x rate)
__device__ __forceinline__ void mma16h(uint32_t* c, const uint32_t* a, const uint32_t* b) {
    asm volatile(
        "mma.sync.aligned.m16n8k16.row.col.f16.f16.f16.f16 "
        "{%0,%1}, {%2,%3,%4,%5}, {%6,%7}, {%0,%1};\n"
        : "+r"(c[0]), "+r"(c[1])
        : "r"(a[0]), "r"(a[1]), "r"(a[2]), "r"(a[3]), "r"(b[0]), "r"(b[1]));
}
#define LDSM_X4(r0, r1, r2, r3, addr)                                       \
    asm volatile("ldmatrix.sync.aligned.m8n8.x4.shared.b16 "                \
                 "{%0,%1,%2,%3}, [%4];"                                     \
                 : "=r"(r0), "=r"(r1), "=r"(r2), "=r"(r3) : "r"(addr))

// ---------------- FP16x3 tensor-core GEMM (m16n8k16 + ldmatrix) --------------
#define RS_H    40
#define TILE_H  (128 * RS_H)
#define STAGE_H (4 * TILE_H)
#define G6_SMEM (2 * STAGE_H * 2)

template<int EPI, int SPLITK>
__global__ __launch_bounds__(256, 2) void gemm_f16x3(
    const __half* __restrict__ Ahi, const __half* __restrict__ Alo, int lda,
    const __half* __restrict__ Bhi, const __half* __restrict__ Blo, int ldb,
    float* __restrict__ C, int ldc, int M, int N, int K,
    const float* __restrict__ bias, const float* __restrict__ res)
{
    extern __shared__ __half sm[];
    int tid = threadIdx.x;
    int m0 = blockIdx.y * 128;
    int n0 = blockIdx.x * 128;

    if (SPLITK > 1) {
        int z = blockIdx.z;
        int Ks = K / SPLITK;
        Ahi += (size_t)z * Ks; Alo += (size_t)z * Ks;
        Bhi += (size_t)z * Ks; Blo += (size_t)z * Ks;
        C += (size_t)z * M * ldc;
        K = Ks;
    }
    int KT = K / 32;

    int lane = tid & 31, wid = tid >> 5;
    int p = lane >> 2, q = lane & 3;
    int wm = (wid & 1) * 64;
    int wn = (wid >> 1) * 32;

    float acc[4][4][4];          // main hi*hi, fp32
    uint32_t cac[4][4][2];       // cross terms, fp16 accumulator (half2 x2)
    #pragma unroll
    for (int i = 0; i < 4; i++)
        #pragma unroll
        for (int j = 0; j < 4; j++) {
            #pragma unroll
            for (int r = 0; r < 4; r++) acc[i][j][r] = 0.f;
            cac[i][j][0] = 0u; cac[i][j][1] = 0u;
        }

    auto load_stage = [&](int kt, int slot) {
        __half* base = sm + slot * STAGE_H;
        int k0 = kt * 32;
        #pragma unroll
        for (int c = tid; c < 2048; c += 256) {
            int tile = c >> 9;
            int r = (c & 511) >> 2;
            int j = c & 3;
            __half* dst = base + tile * TILE_H + r * RS_H + j * 8;
            if (tile < 2) {
                const __half* src = (tile == 0 ? Ahi : Alo)
                                  + (size_t)(m0 + r) * lda + k0 + j * 8;
                cp16(dst, src, 16);
            } else {
                int n = n0 + r;
                int sz = (n < N) ? 16 : 0;
                int rr = sz ? n : 0;
                const __half* src = (tile == 2 ? Bhi : Blo)
                                  + (size_t)rr * ldb + k0 + j * 8;
                cp16(dst, src, sz);
            }
        }
    };

    load_stage(0, 0); cp_commit();
    if (KT > 1) load_stage(1, 1);
    cp_commit();

    uint32_t smbase = (uint32_t)__cvta_generic_to_shared(sm);
    uint32_t a_off = ((wm + (lane & 15)) * RS_H + (lane >> 4) * 8) * 2;
    uint32_t b_off = ((wn + (lane >> 4) * 8 + (lane & 7)) * RS_H
                      + ((lane >> 3) & 1) * 8) * 2;

    for (int kt = 0; kt < KT; kt++) {
        int slot = kt & 1;
        cp_wait<1>();
        __syncthreads();

        uint32_t st = smbase + slot * STAGE_H * 2;
        uint32_t aHi = st + a_off;
        uint32_t aLo = aHi + TILE_H * 2;
        uint32_t bHi = st + 2 * TILE_H * 2 + b_off;
        uint32_t bLo = bHi + TILE_H * 2;

        #pragma unroll
        for (int s = 0; s < 2; s++) {
            uint32_t ko = s * 32;
            uint32_t bh[4][2], bl[4][2];
            LDSM_X4(bh[0][0], bh[0][1], bh[1][0], bh[1][1], bHi + ko);
            LDSM_X4(bh[2][0], bh[2][1], bh[3][0], bh[3][1], bHi + 16 * RS_H * 2 + ko);
            LDSM_X4(bl[0][0], bl[0][1], bl[1][0], bl[1][1], bLo + ko);
            LDSM_X4(bl[2][0], bl[2][1], bl[3][0], bl[3][1], bLo + 16 * RS_H * 2 + ko);
            #pragma unroll
            for (int mi = 0; mi < 4; mi++) {
                uint32_t ah[4], al[4];
                LDSM_X4(ah[0], ah[1], ah[2], ah[3], aHi + mi * 16 * RS_H * 2 + ko);
                LDSM_X4(al[0], al[1], al[2], al[3], aLo + mi * 16 * RS_H * 2 + ko);
                #pragma unroll
                for (int ni = 0; ni < 4; ni++) {
                    mma16(acc[mi][ni], ah, bh[ni]);      // hi*hi -> fp32 acc
                    mma16h(cac[mi][ni], al, bh[ni]);     // lo*hi -> fp16 acc
                    mma16h(cac[mi][ni], ah, bl[ni]);     // hi*lo -> fp16 acc
                }
            }
        }
        __syncthreads();
        if (kt + 2 < KT) load_stage(kt + 2, slot);
        cp_commit();
    }

    #pragma unroll
    for (int mi = 0; mi < 4; mi++) {
        int row = m0 + wm + mi * 16 + p;
        #pragma unroll
        for (int ni = 0; ni < 4; ni++) {
            int col = n0 + wn + ni * 8 + q * 2;
            if (col < N) {
                __half2 cx0 = *(__half2*)&cac[mi][ni][0];
                __half2 cx1 = *(__half2*)&cac[mi][ni][1];
                float v[4] = { acc[mi][ni][0] + __low2float(cx0),
                               acc[mi][ni][1] + __high2float(cx0),
                               acc[mi][ni][2] + __low2float(cx1),
                               acc[mi][ni][3] + __high2float(cx1) };
                if (EPI == 1) {
                    #pragma unroll
                    for (int r = 0; r < 4; r++) {
                        float t = v[r] + bias[col + (r & 1)];
                        float e = __expf(t);
                        v[r] = (t > 15.f) ? t : log1pf(e);
                    }
                } else if (EPI == 2) {
                    v[0] += res[(size_t)row * ldc + col];
                    v[1] += res[(size_t)row * ldc + col + 1];
                    v[2] += res[(size_t)(row + 8) * ldc + col];
                    v[3] += res[(size_t)(row + 8) * ldc + col + 1];
                }
                float* c0 = C + (size_t)row * ldc + col;
                float* c1 = C + (size_t)(row + 8) * ldc + col;
                c0[0] = v[0]; c0[1] = v[1];
                c1[0] = v[2]; c1[1] = v[3];
            }
        }
    }
}

// ---------------- weight hi/lo split (8 elems/thread, 16B stores) ------------
__global__ __launch_bounds__(256) void split_kernel(
    const float* __restrict__ src, __half* __restrict__ hi,
    __half* __restrict__ lo, int n)
{
    int i = (blockIdx.x * 256 + threadIdx.x) * 8;
    if (i >= n) return;
    float4 a = *(const float4*)(src + i);
    float4 b = *(const float4*)(src + i + 4);
    uint2 h0, l0, h1, l1;
    h_split4(a, h0, l0);
    h_split4(b, h1, l1);
    *(uint4*)(hi + i) = make_uint4(h0.x, h0.y, h1.x, h1.y);
    *(uint4*)(lo + i) = make_uint4(l0.x, l0.y, l1.x, l1.y);
}

// ---------------- LayerNorm (8B packed half stores) --------------------------
__global__ __launch_bounds__(256) void ln_kernel(
    const float* __restrict__ x, const float* __restrict__ g,
    const float* __restrict__ b, __half* __restrict__ ohi, __half* __restrict__ olo)
{
    int row = blockIdx.x;
    const float4* xr = (const float4*)(x + (size_t)row * D_MODEL);
    float4 v = xr[threadIdx.x];
    float s  = v.x + v.y + v.z + v.w;
    float ss = v.x*v.x + v.y*v.y + v.z*v.z + v.w*v.w;
    #pragma unroll
    for (int o = 16; o; o >>= 1) {
        s  += __shfl_xor_sync(0xffffffffu, s, o);
        ss += __shfl_xor_sync(0xffffffffu, ss, o);
    }
    __shared__ float red[16];
    __shared__ float mu_s, rstd_s;
    int w = threadIdx.x >> 5, lane = threadIdx.x & 31;
    if (lane == 0) { red[w] = s; red[8 + w] = ss; }
    __syncthreads();
    if (threadIdx.x == 0) {
        float S = 0.f, SS = 0.f;
        #pragma unroll
        for (int i = 0; i < 8; i++) { S += red[i]; SS += red[8 + i]; }
        float mu = S * (1.f / D_MODEL);
        float var = SS * (1.f / D_MODEL) - mu * mu;
        mu_s = mu; rstd_s = rsqrtf(var + 1e-5f);
    }
    __syncthreads();
    float mu = mu_s, r = rstd_s;
    float4 gv = ((const float4*)g)[threadIdx.x];
    float4 bv = ((const float4*)b)[threadIdx.x];
    float4 o;
    o.x = (v.x - mu) * r * gv.x + bv.x;
    o.y = (v.y - mu) * r * gv.y + bv.y;
    o.z = (v.z - mu) * r * gv.z + bv.z;
    o.w = (v.w - mu) * r * gv.w + bv.w;
    uint2 h, l;
    h_split4(o, h, l);
    ((uint2*)(ohi + (size_t)row * D_MODEL))[threadIdx.x] = h;
    ((uint2*)(olo + (size_t)row * D_MODEL))[threadIdx.x] = l;
}

// ---------------- split-K reduce for x_proj (float4) --------------------------
__global__ __launch_bounds__(256) void xproj_reduce(
    const float* __restrict__ part, float* __restrict__ out,
    __half* __restrict__ ohi, __half* __restrict__ olo)
{
    int i = (blockIdx.x * 256 + threadIdx.x) * 4;
    if (i >= BL * XDBL_C) return;
    const int stride = BL * XDBL_C;
    float4 s = *(const float4*)(part + i);
    #pragma unroll
    for (int z = 1; z < XPROJ_SPLITK; z++) {
        float4 p = *(const float4*)(part + z * stride + i);
        s.x += p.x; s.y += p.y; s.z += p.z; s.w += p.w;
    }
    *(float4*)(out + i) = s;
    uint2 h, l;
    h_split4(s, h, l);
    *(uint2*)(ohi + i) = h;
    *(uint2*)(olo + i) = l;
}

// ---------------- causal depthwise conv (K=4) + SiLU, 4 ch/thread ------------
__global__ __launch_bounds__(256) void conv_silu_kernel(
    const float* __restrict__ xz, const float* __restrict__ w,
    const float* __restrict__ bias,
    __half* __restrict__ uhi, __half* __restrict__ ulo)
{
    int idx = blockIdx.x * 256 + threadIdx.x;
    if (idx >= BL * D_INNER / 4) return;
    int d4 = (idx * 4) % D_INNER;
    int t  = (idx * 4 / D_INNER) % SEQ;
    int b  = idx * 4 / (D_INNER * SEQ);

    float4 acc = *(const float4*)(bias + d4);
    float4 wr[4];
    #pragma unroll
    for (int c = 0; c < 4; c++) wr[c] = *(const float4*)(w + (d4 + c) * CONV_K);

    #pragma unroll
    for (int k = 0; k < CONV_K; k++) {
        int ts = t - (CONV_K - 1) + k;
        if (ts >= 0) {
            float4 xv = *(const float4*)(xz + (size_t)(b * SEQ + ts) * (2 * D_INNER) + d4);
            acc.x += ((const float*)&wr[0])[k] * xv.x;
            acc.y += ((const float*)&wr[1])[k] * xv.y;
            acc.z += ((const float*)&wr[2])[k] * xv.z;
            acc.w += ((const float*)&wr[3])[k] * xv.w;
        }
    }
    float4 val;
    val.x = acc.x / (1.f + __expf(-acc.x));
    val.y = acc.y / (1.f + __expf(-acc.y));
    val.z = acc.z / (1.f + __expf(-acc.z));
    val.w = acc.w / (1.f + __expf(-acc.w));
    size_t oi = (size_t)(b * SEQ + t) * D_INNER + d4;
    uint2 h, l;
    h_split4(val, h, l);
    *(uint2*)(uhi + oi) = h;
    *(uint2*)(ulo + oi) = l;
}

// ---------------- selective scan (gate fused; u from hi/lo) -------------------
#define SC_DC 32
#define SC_TC 64
__global__ __launch_bounds__(SC_DC * D_STATE) void scan_kernel(
    const __half* __restrict__ uhi, const __half* __restrict__ ulo,
    const float* __restrict__ dl,
    const float* __restrict__ xdbl, const float* __restrict__ A_log,
    const float* __restrict__ xz, const float* __restrict__ Dp,
    __half* __restrict__ yhi, __half* __restrict__ ylo)
{
    __shared__ float u_s [SC_TC][SC_DC];
    __shared__ float dl_s[SC_TC][SC_DC];
    __shared__ float B_s [SC_TC][D_STATE];
    __shared__ float C_s [SC_TC][D_STATE];
    __shared__ float y_s [SC_TC][SC_DC];

    int b  = blockIdx.y;
    int d0 = blockIdx.x * SC_DC;
    int tid = threadIdx.x;
    int g = tid >> 4;
    int n = tid & 15;
    int d = d0 + g;

    float a = -expf(A_log[d * D_STATE + n]);
    float s = 0.f;

    for (int t0 = 0; t0 < SEQ; t0 += SC_TC) {
        {
            int i = tid * 4;
            int tt = i >> 5, gg = i & 31;
            size_t gi = (size_t)(b * SEQ + t0 + tt) * D_INNER + d0 + gg;
            uint2 uh = *(const uint2*)(uhi + gi);
            uint2 ul = *(const uint2*)(ulo + gi);
            __half2 h0 = *(__half2*)&uh.x, h1 = *(__half2*)&uh.y;
            __half2 l0 = *(__half2*)&ul.x, l1 = *(__half2*)&ul.y;
            float4 uu;
            uu.x = __low2float(h0)  + __low2float(l0);
            uu.y = __high2float(h0) + __high2float(l0);
            uu.z = __low2float(h1)  + __low2float(l1);
            uu.w = __high2float(h1) + __high2float(l1);
            *(float4*)&u_s[tt][gg] = uu;
            *(float4*)&dl_s[tt][gg] = *(const float4*)(dl + gi);
        }
        {
            int i = tid * 4;
            int tt = i >> 5, pos = i & 31;
            const float* r = xdbl + (size_t)(b * SEQ + t0 + tt) * XDBL_C + DT_RANK;
            float4 v = *(const float4*)(r + pos);
            if (pos < 16) *(float4*)&B_s[tt][pos] = v;
            else          *(float4*)&C_s[tt][pos - 16] = v;
        }
        __syncthreads();
        #pragma unroll 4
        for (int t = 0; t < SC_TC; t++) {
            float dlt = dl_s[t][g];
            float dA  = __expf(dlt * a);
            float dbu = dlt * B_s[t][n] * u_s[t][g];
            s = fmaf(dA, s, dbu);
            float part = s * C_s[t][n];
            part += __shfl_xor_sync(0xffffffffu, part, 8);
            part += __shfl_xor_sync(0xffffffffu, part, 4);
            part += __shfl_xor_sync(0xffffffffu, part, 2);
            part += __shfl_xor_sync(0xffffffffu, part, 1);
            if (n == 0) y_s[t][g] = part;
        }
        __syncthreads();
        {
            int i = tid * 4;
            int tt = i >> 5, gg = i & 31;
            int rowg = b * SEQ + t0 + tt;
            float4 z = *(const float4*)(xz + (size_t)rowg * (2 * D_INNER) + D_INNER + d0 + gg);
            float4 uu = *(const float4*)&u_s[tt][gg];
            float4 yy = *(const float4*)&y_s[tt][gg];
            float4 dp = *(const float4*)(Dp + d0 + gg);
            float4 val;
            val.x = (yy.x + uu.x * dp.x) * (z.x / (1.f + __expf(-z.x)));
            val.y = (yy.y + uu.y * dp.y) * (z.y / (1.f + __expf(-z.y)));
            val.z = (yy.z + uu.z * dp.z) * (z.z / (1.f + __expf(-z.z)));
            val.w = (yy.w + uu.w * dp.w) * (z.w / (1.f + __expf(-z.w)));
            uint2 h, l;
            h_split4(val, h, l);
            size_t oi = (size_t)rowg * D_INNER + d0 + gg;
            *(uint2*)(yhi + oi) = h;
            *(uint2*)(ylo + oi) = l;
        }
        __syncthreads();
    }
}

// ---------------- launch ------------------------------------------------------
extern "C" void kernel_launch(void* const* d_in, const int* in_sizes, int n_in,
                              void* d_out, int out_size)
{
    const float* x      = (const float*)d_in[0];
    const float* ln_g   = (const float*)d_in[1];
    const float* ln_b   = (const float*)d_in[2];
    const float* W_in   = (const float*)d_in[3];
    const float* conv_w = (const float*)d_in[4];
    const float* conv_b = (const float*)d_in[5];
    const float* A_log  = (const float*)d_in[6];
    const float* D_prm  = (const float*)d_in[7];
    const float* x_proj = (const float*)d_in[8];
    const float* dt_w   = (const float*)d_in[9];
    const float* dt_b   = (const float*)d_in[10];
    const float* W_out  = (const float*)d_in[11];
    float* out = (float*)d_out;

    __half *xn_hi, *xn_lo, *u_hi, *u_lo, *xd_hi, *xd_lo, *y_hi, *y_lo;
    __half *wi_hi, *wi_lo, *xp_hi, *xp_lo, *dw_hi, *dw_lo, *wo_hi, *wo_lo;
    float *xz, *xdbl, *part, *dl;
    cudaGetSymbolAddress((void**)&xn_hi, g_xn_hi);
    cudaGetSymbolAddress((void**)&xn_lo, g_xn_lo);
    cudaGetSymbolAddress((void**)&xz,    g_xz);
    cudaGetSymbolAddress((void**)&u_hi,  g_u_hi);
    cudaGetSymbolAddress((void**)&u_lo,  g_u_lo);
    cudaGetSymbolAddress((void**)&xdbl,  g_xdbl);
    cudaGetSymbolAddress((void**)&xd_hi, g_xd_hi);
    cudaGetSymbolAddress((void**)&xd_lo, g_xd_lo);
    cudaGetSymbolAddress((void**)&part,  g_part);
    cudaGetSymbolAddress((void**)&dl,    g_dl);
    cudaGetSymbolAddress((void**)&y_hi,  g_y_hi);
    cudaGetSymbolAddress((void**)&y_lo,  g_y_lo);
    cudaGetSymbolAddress((void**)&wi_hi, g_wi_hi);
    cudaGetSymbolAddress((void**)&wi_lo, g_wi_lo);
    cudaGetSymbolAddress((void**)&xp_hi, g_xp_hi);
    cudaGetSymbolAddress((void**)&xp_lo, g_xp_lo);
    cudaGetSymbolAddress((void**)&dw_hi, g_dw_hi);
    cudaGetSymbolAddress((void**)&dw_lo, g_dw_lo);
    cudaGetSymbolAddress((void**)&wo_hi, g_wo_hi);
    cudaGetSymbolAddress((void**)&wo_lo, g_wo_lo);

    cudaFuncSetAttribute(gemm_f16x3<0,1>, cudaFuncAttributeMaxDynamicSharedMemorySize, G6_SMEM);
    cudaFuncSetAttribute(gemm_f16x3<0,XPROJ_SPLITK>, cudaFuncAttributeMaxDynamicSharedMemorySize, G6_SMEM);
    cudaFuncSetAttribute(gemm_f16x3<1,1>, cudaFuncAttributeMaxDynamicSharedMemorySize, G6_SMEM);
    cudaFuncSetAttribute(gemm_f16x3<2,1>, cudaFuncAttributeMaxDynamicSharedMemorySize, G6_SMEM);

    // 0. weight hi/lo splits
    split_kernel<<<(2*D_INNER*D_MODEL/8 + 255)/256, 256>>>(W_in,  wi_hi, wi_lo, 2*D_INNER*D_MODEL);
    split_kernel<<<(XDBL_C*D_INNER/8   + 255)/256, 256>>>(x_proj, xp_hi, xp_lo, XDBL_C*D_INNER);
    split_kernel<<<(D_INNER*DT_RANK/8  + 255)/256, 256>>>(dt_w,   dw_hi, dw_lo, D_INNER*DT_RANK);
    split_kernel<<<(D_MODEL*D_INNER/8  + 255)/256, 256>>>(W_out,  wo_hi, wo_lo, D_MODEL*D_INNER);

    // 1. LayerNorm -> xn hi/lo
    ln_kernel<<<BL, 256>>>(x, ln_g, ln_b, xn_hi, xn_lo);

    // 2. xz = xn @ W_in^T   (4096 x 4096 x 1024)
    gemm_f16x3<0,1><<<dim3(2*D_INNER/128, BL/128), 256, G6_SMEM>>>(
        xn_hi, xn_lo, D_MODEL, wi_hi, wi_lo, D_MODEL,
        xz, 2*D_INNER, BL, 2*D_INNER, D_MODEL, nullptr, nullptr);

    // 3. causal depthwise conv + SiLU -> u hi/lo
    conv_silu_kernel<<<(BL*D_INNER/4 + 255)/256, 256>>>(xz, conv_w, conv_b, u_hi, u_lo);

    // 4. x_dbl = u @ x_proj^T  (4096 x 96 x 2048), split-K=4
    gemm_f16x3<0,XPROJ_SPLITK><<<dim3(1, BL/128, XPROJ_SPLITK), 256, G6_SMEM>>>(
        u_hi, u_lo, D_INNER, xp_hi, xp_lo, D_INNER,
        part, XDBL_C, BL, XDBL_C, D_INNER, nullptr, nullptr);
    xproj_reduce<<<(BL*XDBL_C/4 + 255)/256, 256>>>(part, xdbl, xd_hi, xd_lo);

    // 5. delta = softplus(dt_r @ dt_w^T + dt_b)  (4096 x 2048 x 64)
    gemm_f16x3<1,1><<<dim3(D_INNER/128, BL/128), 256, G6_SMEM>>>(
        xd_hi, xd_lo, XDBL_C, dw_hi, dw_lo, DT_RANK,
        dl, D_INNER, BL, D_INNER, DT_RANK, dt_b, nullptr);

    // 6. selective scan + fused gate -> y hi/lo
    scan_kernel<<<dim3(D_INNER/SC_DC, BSZ), SC_DC*D_STATE>>>(
        u_hi, u_lo, dl, xdbl, A_log, xz, D_prm, y_hi, y_lo);

    // 7. out = y @ W_out^T + x  (4096 x 1024 x 2048)
    gemm_f16x3<2,1><<<dim3(D_MODEL/128, BL/128), 256, G6_SMEM>>>(
        y_hi, y_lo, D_INNER, wo_hi, wo_lo, D_INNER,
        out, D_MODEL, BL, D_MODEL, D_INNER, nullptr, x);
}